// round 1
// baseline (speedup 1.0000x reference)
#include <cuda_runtime.h>

// LIF recurrence over the contiguous time axis.
// x: [B*N, T] fp32, T=100. Per neuron:
//   u_t = decay*u_{t-1} + x_t - o_{t-1}*VTH ; o_t = (u_t - VTH > 0) ? 1 : 0
// One thread per neuron; T contiguous -> float4 loads/stores (400B row, 16B aligned).

#define VTH 0.5f
#define T_STEPS 100
#define T_VEC (T_STEPS / 4)

__global__ void __launch_bounds__(256) lif_kernel(
    const float* __restrict__ x,
    const float* __restrict__ decay_p,
    float* __restrict__ out,
    int n_neurons)
{
    int i = blockIdx.x * blockDim.x + threadIdx.x;
    if (i >= n_neurons) return;

    const float decay = __ldg(decay_p);

    const float4* __restrict__ xr =
        reinterpret_cast<const float4*>(x + (size_t)i * T_STEPS);
    float4* __restrict__ orow =
        reinterpret_cast<float4*>(out + (size_t)i * T_STEPS);

    float u = 0.0f;
    float o = 0.0f;

#pragma unroll 5
    for (int t = 0; t < T_VEC; ++t) {
        float4 xv = xr[t];
        float4 ov;

        u = fmaf(decay, u, xv.x) - o * VTH;
        o = (u > VTH) ? 1.0f : 0.0f;
        ov.x = o;

        u = fmaf(decay, u, xv.y) - o * VTH;
        o = (u > VTH) ? 1.0f : 0.0f;
        ov.y = o;

        u = fmaf(decay, u, xv.z) - o * VTH;
        o = (u > VTH) ? 1.0f : 0.0f;
        ov.z = o;

        u = fmaf(decay, u, xv.w) - o * VTH;
        o = (u > VTH) ? 1.0f : 0.0f;
        ov.w = o;

        orow[t] = ov;
    }
}

extern "C" void kernel_launch(void* const* d_in, const int* in_sizes, int n_in,
                              void* d_out, int out_size)
{
    const float* x       = (const float*)d_in[0];
    const float* decay_p = (const float*)d_in[1];
    float*       out     = (float*)d_out;

    int n_neurons = in_sizes[0] / T_STEPS;  // 64*4096 = 262144

    const int block = 256;
    const int grid  = (n_neurons + block - 1) / block;
    lif_kernel<<<grid, block>>>(x, decay_p, out, n_neurons);
}

// round 2
// speedup vs baseline: 2.0249x; 2.0249x over previous
#include <cuda_runtime.h>

// LIF recurrence, smem-staged for coalescing.
// x: [B*N, T] fp32, T=100 contiguous. Per neuron:
//   u_t = decay*u_{t-1} + x_t - o_{t-1}*VTH ; o_t = (u_t - VTH > 0) ? 1 : 0
//
// Each warp owns 32 consecutive rows = one contiguous 12800B global span.
// Phase 1: coalesced float4 copy gmem -> smem (identity layout, stride 100).
// Phase 2: lane j scans row j from smem (LDS.128), recurrence in registers,
//          writes spikes back in place (STS.128).
// Phase 3: coalesced float4 copy smem -> gmem.

#define VTH 0.5f
#define T_STEPS 100
#define T_VEC (T_STEPS / 4)          // 25
#define ROWS_PER_WARP 32
#define WARPS_PER_BLOCK 2
#define BLOCK_THREADS (WARPS_PER_BLOCK * 32)
#define TILE_FLOATS (ROWS_PER_WARP * T_STEPS)   // 3200 floats = 12800 B
#define TILE_VEC (TILE_FLOATS / 4)              // 800 float4

__global__ void __launch_bounds__(BLOCK_THREADS) lif_kernel(
    const float* __restrict__ x,
    const float* __restrict__ decay_p,
    float* __restrict__ out,
    int n_neurons)
{
    extern __shared__ float smem[];  // WARPS_PER_BLOCK * TILE_FLOATS

    const int warp = threadIdx.x >> 5;
    const int lane = threadIdx.x & 31;

    const int base_row = (blockIdx.x * WARPS_PER_BLOCK + warp) * ROWS_PER_WARP;
    if (base_row >= n_neurons) return;

    const float decay = __ldg(decay_p);

    float* tile = smem + warp * TILE_FLOATS;
    float4* tile4 = reinterpret_cast<float4*>(tile);

    // ---- Phase 1: coalesced load, contiguous identity copy into smem ----
    const float4* __restrict__ gx4 =
        reinterpret_cast<const float4*>(x + (size_t)base_row * T_STEPS);
#pragma unroll
    for (int i = 0; i < TILE_VEC / 32; ++i) {
        int idx = lane + 32 * i;        // 0..799, coalesced
        tile4[idx] = gx4[idx];
    }
    __syncwarp();

    // ---- Phase 2: per-lane scan over its own row (conflict-free LDS.128) ----
    {
        float4* mrow4 = reinterpret_cast<float4*>(tile + lane * T_STEPS);
        float u = 0.0f;
        float o = 0.0f;
#pragma unroll
        for (int t4 = 0; t4 < T_VEC; ++t4) {
            float4 xv = mrow4[t4];
            float4 ov;

            u = fmaf(decay, u, xv.x);
            u = fmaf(-VTH, o, u);
            o = (u > VTH) ? 1.0f : 0.0f;
            ov.x = o;

            u = fmaf(decay, u, xv.y);
            u = fmaf(-VTH, o, u);
            o = (u > VTH) ? 1.0f : 0.0f;
            ov.y = o;

            u = fmaf(decay, u, xv.z);
            u = fmaf(-VTH, o, u);
            o = (u > VTH) ? 1.0f : 0.0f;
            ov.z = o;

            u = fmaf(decay, u, xv.w);
            u = fmaf(-VTH, o, u);
            o = (u > VTH) ? 1.0f : 0.0f;
            ov.w = o;

            mrow4[t4] = ov;   // overwrite consumed input in place
        }
    }
    __syncwarp();

    // ---- Phase 3: coalesced store, contiguous identity copy from smem ----
    float4* __restrict__ go4 =
        reinterpret_cast<float4*>(out + (size_t)base_row * T_STEPS);
#pragma unroll
    for (int i = 0; i < TILE_VEC / 32; ++i) {
        int idx = lane + 32 * i;
        go4[idx] = tile4[idx];
    }
}

extern "C" void kernel_launch(void* const* d_in, const int* in_sizes, int n_in,
                              void* d_out, int out_size)
{
    const float* x       = (const float*)d_in[0];
    const float* decay_p = (const float*)d_in[1];
    float*       out     = (float*)d_out;

    int n_neurons = in_sizes[0] / T_STEPS;  // 262144

    int rows_per_block = WARPS_PER_BLOCK * ROWS_PER_WARP;       // 64
    int grid = (n_neurons + rows_per_block - 1) / rows_per_block;
    size_t smem_bytes = WARPS_PER_BLOCK * TILE_FLOATS * sizeof(float);  // 25600 B

    lif_kernel<<<grid, BLOCK_THREADS, smem_bytes>>>(x, decay_p, out, n_neurons);
}

// round 3
// speedup vs baseline: 2.4024x; 1.1865x over previous
#include <cuda_runtime.h>
#include <cstdint>

// LIF recurrence, cp.async-staged, 2 rows per thread for chain ILP.
// x: [B*N, T] fp32, T=100 contiguous.
//   u_t = decay*u_{t-1} + x_t - o_{t-1}*VTH ; o_t = (u_t - VTH > 0) ? 1 : 0
//
// Warp tile: 64 consecutive rows = 25600B contiguous gmem span.
//  Phase 1: cp.async (LDGSTS.128) gmem -> smem, whole tile in flight at once.
//  Phase 2: thread scans rows (lane) and (lane+32): two interleaved chains.
//           Spikes overwrite the input tile in place.
//  Phase 3: coalesced float4 copy smem -> gmem.

#define VTH 0.5f
#define T_STEPS 100
#define T_VEC (T_STEPS / 4)            // 25
#define ROWS_PER_WARP 64
#define WARPS_PER_BLOCK 2
#define BLOCK_THREADS (WARPS_PER_BLOCK * 32)
#define TILE_FLOATS (ROWS_PER_WARP * T_STEPS)      // 6400 floats = 25600 B
#define TILE_VEC (TILE_FLOATS / 4)                 // 1600 float4
#define VEC_PER_LANE (TILE_VEC / 32)               // 50
#define SMEM_BYTES (WARPS_PER_BLOCK * TILE_FLOATS * sizeof(float))  // 51200

__device__ __forceinline__ void cp_async16(uint32_t smem_dst, const void* gmem_src) {
    asm volatile("cp.async.cg.shared.global [%0], [%1], 16;\n"
                 :: "r"(smem_dst), "l"(gmem_src));
}
__device__ __forceinline__ void cp_async_commit() {
    asm volatile("cp.async.commit_group;\n" ::: "memory");
}
__device__ __forceinline__ void cp_async_wait_all() {
    asm volatile("cp.async.wait_group 0;\n" ::: "memory");
}

#define LIF_STEP(u, o, xv)                      \
    do {                                        \
        u = fmaf(decay, u, xv);                 \
        u = fmaf(-VTH, o, u);                   \
        o = (u > VTH) ? 1.0f : 0.0f;            \
    } while (0)

__global__ void __launch_bounds__(BLOCK_THREADS) lif_kernel(
    const float* __restrict__ x,
    const float* __restrict__ decay_p,
    float* __restrict__ out,
    int n_neurons)
{
    extern __shared__ float smem[];

    const int warp = threadIdx.x >> 5;
    const int lane = threadIdx.x & 31;

    const int base_row = (blockIdx.x * WARPS_PER_BLOCK + warp) * ROWS_PER_WARP;
    if (base_row >= n_neurons) return;

    const float decay = __ldg(decay_p);

    float* tile = smem + warp * TILE_FLOATS;
    uint32_t tile_s = (uint32_t)__cvta_generic_to_shared(tile);

    // ---- Phase 1: whole tile via cp.async, all 50 x 16B per lane in flight ----
    const float4* __restrict__ gx4 =
        reinterpret_cast<const float4*>(x + (size_t)base_row * T_STEPS);
#pragma unroll
    for (int i = 0; i < VEC_PER_LANE; ++i) {
        int idx = lane + 32 * i;                       // coalesced, contiguous span
        cp_async16(tile_s + idx * 16u, gx4 + idx);
    }
    cp_async_commit();
    cp_async_wait_all();
    __syncwarp();

    // ---- Phase 2: two interleaved scans per thread (rows lane, lane+32) ----
    {
        float4* r0 = reinterpret_cast<float4*>(tile + (size_t)lane * T_STEPS);
        float4* r1 = reinterpret_cast<float4*>(tile + (size_t)(lane + 32) * T_STEPS);

        float u0 = 0.0f, o0 = 0.0f;
        float u1 = 0.0f, o1 = 0.0f;

#pragma unroll
        for (int t4 = 0; t4 < T_VEC; ++t4) {
            float4 a = r0[t4];
            float4 b = r1[t4];
            float4 oa, ob;

            LIF_STEP(u0, o0, a.x);  oa.x = o0;
            LIF_STEP(u1, o1, b.x);  ob.x = o1;
            LIF_STEP(u0, o0, a.y);  oa.y = o0;
            LIF_STEP(u1, o1, b.y);  ob.y = o1;
            LIF_STEP(u0, o0, a.z);  oa.z = o0;
            LIF_STEP(u1, o1, b.z);  ob.z = o1;
            LIF_STEP(u0, o0, a.w);  oa.w = o0;
            LIF_STEP(u1, o1, b.w);  ob.w = o1;

            r0[t4] = oa;           // overwrite consumed input in place
            r1[t4] = ob;
        }
    }
    __syncwarp();

    // ---- Phase 3: coalesced store ----
    const float4* tile4 = reinterpret_cast<const float4*>(tile);
    float4* __restrict__ go4 =
        reinterpret_cast<float4*>(out + (size_t)base_row * T_STEPS);
#pragma unroll
    for (int i = 0; i < VEC_PER_LANE; ++i) {
        int idx = lane + 32 * i;
        go4[idx] = tile4[idx];
    }
}

extern "C" void kernel_launch(void* const* d_in, const int* in_sizes, int n_in,
                              void* d_out, int out_size)
{
    const float* x       = (const float*)d_in[0];
    const float* decay_p = (const float*)d_in[1];
    float*       out     = (float*)d_out;

    int n_neurons = in_sizes[0] / T_STEPS;  // 262144

    cudaFuncSetAttribute(lif_kernel,
                         cudaFuncAttributeMaxDynamicSharedMemorySize,
                         (int)SMEM_BYTES);

    int rows_per_block = WARPS_PER_BLOCK * ROWS_PER_WARP;      // 128
    int grid = (n_neurons + rows_per_block - 1) / rows_per_block;  // 2048

    lif_kernel<<<grid, BLOCK_THREADS, SMEM_BYTES>>>(x, decay_p, out, n_neurons);
}